// round 9
// baseline (speedup 1.0000x reference)
#include <cuda_runtime.h>
#include <cuda_fp16.h>
#include <math.h>

#define NMAX 100000
#define FD   64
#define EMAX 1000000

// ---------------------------------------------------------------------------
// Scratch (__device__ globals; no allocation allowed)
// ---------------------------------------------------------------------------
__device__ __align__(256) __half g_z[NMAX * FD];   // dinv-scaled transformed feats (fp16)
__device__ __align__(256) float  g_h[NMAX * FD];   // layer-1 output (relu'd, fp32)
__device__ float g_dinv[NMAX];
__device__ int   g_cnt[NMAX];
__device__ int   g_start[NMAX];
__device__ int   g_cursor[NMAX];
__device__ int   g_srcs[EMAX];
__device__ int   g_bsum[1024];
__device__ int   g_bar_arrive;    // zero-init; returns to 0 after each barrier
__device__ int   g_bar_gen;       // monotonically increasing generation

// ---------------------------------------------------------------------------
// Grid-wide barrier (all blocks co-resident by construction).
// ---------------------------------------------------------------------------
__device__ __forceinline__ void gbar(int nblocks) {
    __syncthreads();
    if (threadIdx.x == 0) {
        __threadfence();                                    // release my writes
        int gen = *(volatile int*)&g_bar_gen;               // read BEFORE arriving
        if (atomicAdd(&g_bar_arrive, 1) == nblocks - 1) {
            *(volatile int*)&g_bar_arrive = 0;
            __threadfence();
            atomicAdd(&g_bar_gen, 1);
        } else {
            while (*(volatile int*)&g_bar_gen == gen) {}
        }
        __threadfence();                                    // acquire others' writes
    }
    __syncthreads();
}

// ---------------------------------------------------------------------------
// In-block inclusive scan (Hillis-Steele), 256 threads.
// ---------------------------------------------------------------------------
__device__ __forceinline__ int block_scan_incl(int v, int* sh) {
    int t = threadIdx.x;
    sh[t] = v; __syncthreads();
    #pragma unroll
    for (int off = 1; off < 256; off <<= 1) {
        int x = (t >= off) ? sh[t - off] : 0;
        __syncthreads();
        sh[t] += x;
        __syncthreads();
    }
    return sh[t];
}

// ---------------------------------------------------------------------------
// GEMM phase: Zh[r,:] = half( (X[r,:] @ W) * dinv[r] )
//   64x64 tile per iteration, 256 threads, 4x4 register tile/thread.
// ---------------------------------------------------------------------------
__device__ void gemm_phase(const float* __restrict__ X,
                           const float* __restrict__ W,
                           const float* __restrict__ dinv,
                           __half* __restrict__ Z, int n,
                           float (*Ws)[64], float (*Xst)[68]) {
    int t = threadIdx.x;
    int ntiles = (n + 63) >> 6;

    #pragma unroll
    for (int i = t; i < 1024; i += 256)
        reinterpret_cast<float4*>(&Ws[0][0])[i] = reinterpret_cast<const float4*>(W)[i];
    __syncthreads();

    int tx = t & 15, ty = t >> 4;   // cols tx*4.., rows ty*4..

    for (int tile = blockIdx.x; tile < ntiles; tile += gridDim.x) {
        int r0 = tile << 6;

        #pragma unroll
        for (int q = t; q < 1024; q += 256) {     // 64 rows x 16 quads
            int r  = q >> 4;
            int c4 = (q & 15) * 4;
            int gr = r0 + r;
            float4 v = (gr < n) ? *reinterpret_cast<const float4*>(X + (size_t)gr * FD + c4)
                                : make_float4(0.f, 0.f, 0.f, 0.f);
            Xst[c4 + 0][r] = v.x; Xst[c4 + 1][r] = v.y;
            Xst[c4 + 2][r] = v.z; Xst[c4 + 3][r] = v.w;
        }
        __syncthreads();

        float acc[4][4] = {};
        #pragma unroll
        for (int k = 0; k < 64; k++) {
            float4 xv = *reinterpret_cast<const float4*>(&Xst[k][ty * 4]);
            float4 wv = *reinterpret_cast<const float4*>(&Ws[k][tx * 4]);
            float xr[4] = {xv.x, xv.y, xv.z, xv.w};
            float wc[4] = {wv.x, wv.y, wv.z, wv.w};
            #pragma unroll
            for (int i = 0; i < 4; i++)
                #pragma unroll
                for (int j = 0; j < 4; j++)
                    acc[i][j] = fmaf(xr[i], wc[j], acc[i][j]);
        }

        #pragma unroll
        for (int i = 0; i < 4; i++) {
            int gr = r0 + ty * 4 + i;
            if (gr < n) {
                float s = dinv[gr];
                __half2 hs[2];
                hs[0] = __floats2half2_rn(acc[i][0] * s, acc[i][1] * s);
                hs[1] = __floats2half2_rn(acc[i][2] * s, acc[i][3] * s);
                *reinterpret_cast<uint2*>(Z + (size_t)gr * FD + tx * 4) =
                    *reinterpret_cast<uint2*>(hs);
            }
        }
        __syncthreads();   // protect Xst before next tile
    }
}

// ---------------------------------------------------------------------------
// Aggregation phase (fp16 gathers, fp32 accum):
//   out[c,:] = relu( (zh[c,:] + sum_{r->c} zh[r,:]) * dinv[c] + b )
//   8 lanes per node, 16B per lane.
// ---------------------------------------------------------------------------
__device__ __forceinline__ void acc_add8(float a[8], uint4 v) {
    __half2* p = reinterpret_cast<__half2*>(&v);
    #pragma unroll
    for (int q = 0; q < 4; q++) {
        float2 f = __half22float2(p[q]);
        a[q * 2 + 0] += f.x;
        a[q * 2 + 1] += f.y;
    }
}

__device__ void agg_phase(const __half* __restrict__ zs,
                          const int* __restrict__ srcs,
                          const int* __restrict__ startv,
                          const int* __restrict__ cnt,
                          const float* __restrict__ dinv,
                          const float* __restrict__ bias,
                          float* __restrict__ outp, int n) {
    const uint4* zq = reinterpret_cast<const uint4*>(zs);
    int tid0   = blockIdx.x * blockDim.x + threadIdx.x;
    int stride = gridDim.x * blockDim.x;
    int lane   = tid0 & 7;

    float4 b0 = reinterpret_cast<const float4*>(bias)[lane * 2 + 0];
    float4 b1 = reinterpret_cast<const float4*>(bias)[lane * 2 + 1];

    for (int u = tid0; u < n * 8; u += stride) {
        int node = u >> 3;
        int s = startv[node];
        int m = cnt[node];
        float d = dinv[node];

        float a[8] = {};
        acc_add8(a, zq[(size_t)node * 8 + lane]);   // self loop

        int i = 0;
        for (; i + 4 <= m; i += 4) {
            int r0 = srcs[s + i + 0];
            int r1 = srcs[s + i + 1];
            int r2 = srcs[s + i + 2];
            int r3 = srcs[s + i + 3];
            uint4 v0 = zq[(size_t)r0 * 8 + lane];
            uint4 v1 = zq[(size_t)r1 * 8 + lane];
            uint4 v2 = zq[(size_t)r2 * 8 + lane];
            uint4 v3 = zq[(size_t)r3 * 8 + lane];
            acc_add8(a, v0); acc_add8(a, v1);
            acc_add8(a, v2); acc_add8(a, v3);
        }
        for (; i < m; i++) {
            int r = srcs[s + i];
            acc_add8(a, zq[(size_t)r * 8 + lane]);
        }

        float4 o0 = make_float4(fmaxf(fmaf(a[0], d, b0.x), 0.f),
                                fmaxf(fmaf(a[1], d, b0.y), 0.f),
                                fmaxf(fmaf(a[2], d, b0.z), 0.f),
                                fmaxf(fmaf(a[3], d, b0.w), 0.f));
        float4 o1 = make_float4(fmaxf(fmaf(a[4], d, b1.x), 0.f),
                                fmaxf(fmaf(a[5], d, b1.y), 0.f),
                                fmaxf(fmaf(a[6], d, b1.z), 0.f),
                                fmaxf(fmaf(a[7], d, b1.w), 0.f));
        float4* po = reinterpret_cast<float4*>(outp + (size_t)node * FD + lane * 8);
        po[0] = o0;
        po[1] = o1;
    }
}

// ---------------------------------------------------------------------------
// Mega-kernel: all phases in one launch, grid-wide barriers between.
// ---------------------------------------------------------------------------
__global__ void __launch_bounds__(256, 2)
k_mega(const float* __restrict__ x,
       const int* __restrict__ row, const int* __restrict__ col,
       const float* __restrict__ W1, const float* __restrict__ b1,
       const float* __restrict__ W2, const float* __restrict__ b2,
       float* __restrict__ out, int n, int E) {
    __shared__ float Ws[64][64];
    __shared__ float Xst[64][68];
    __shared__ int   sh[256];

    const int t = threadIdx.x;
    const int gtid = blockIdx.x * 256 + t;
    const int gstride = gridDim.x * 256;
    const int NB = gridDim.x;

    // P0: zero counts
    for (int i = gtid; i < n; i += gstride) g_cnt[i] = 0;
    gbar(NB);

    // P1: in-degree count
    for (int e = gtid; e < E; e += gstride) atomicAdd(&g_cnt[col[e]], 1);
    gbar(NB);

    // P2: per-chunk local exclusive scan (+ dinv fused)
    int nchunks = (n + 255) >> 8;
    for (int c = blockIdx.x; c < nchunks; c += gridDim.x) {
        int i = (c << 8) + t;
        int v = (i < n) ? g_cnt[i] : 0;
        if (i < n) g_dinv[i] = rsqrtf((float)(v + 1));
        int incl = block_scan_incl(v, sh);
        if (i < n) g_start[i] = incl - v;
        if (t == 255) g_bsum[c] = incl;
        __syncthreads();
    }
    gbar(NB);

    // P3: block 0 scans chunk sums (exclusive, carried across 256-chunks)
    if (blockIdx.x == 0) {
        int carry = 0;
        for (int base = 0; base < nchunks; base += 256) {
            int idx = base + t;
            int v = (idx < nchunks) ? g_bsum[idx] : 0;
            int incl = block_scan_incl(v, sh);
            if (idx < nchunks) g_bsum[idx] = incl - v + carry;
            __syncthreads();
            carry += sh[255];
            __syncthreads();
        }
    }
    gbar(NB);

    // P4: finalize starts + init cursors
    for (int i = gtid; i < n; i += gstride) {
        int s = g_start[i] + g_bsum[i >> 8];
        g_start[i] = s;
        g_cursor[i] = s;
    }
    gbar(NB);

    // P5: CSR fill
    for (int e = gtid; e < E; e += gstride) {
        int pos = atomicAdd(&g_cursor[col[e]], 1);
        g_srcs[pos] = row[e];
    }
    gbar(NB);

    // P6/P7: layer 1
    gemm_phase(x, W1, g_dinv, g_z, n, Ws, Xst);
    gbar(NB);
    agg_phase(g_z, g_srcs, g_start, g_cnt, g_dinv, b1, g_h, n);
    gbar(NB);

    // P8/P9: layer 2
    gemm_phase(g_h, W2, g_dinv, g_z, n, Ws, Xst);
    gbar(NB);
    agg_phase(g_z, g_srcs, g_start, g_cnt, g_dinv, b2, out, n);
}

// ---------------------------------------------------------------------------
// Launch: single kernel; grid sized for guaranteed co-residency.
// ---------------------------------------------------------------------------
extern "C" void kernel_launch(void* const* d_in, const int* in_sizes, int n_in,
                              void* d_out, int out_size) {
    const float* x  = (const float*)d_in[0];
    const int*   ei = (const int*)d_in[1];
    const float* W1 = (const float*)d_in[2];
    const float* b1 = (const float*)d_in[3];
    const float* W2 = (const float*)d_in[4];
    const float* b2 = (const float*)d_in[5];
    float*       out = (float*)d_out;

    const int n = in_sizes[0] / FD;     // 100000
    const int E = in_sizes[1] / 2;      // 1000000
    const int* row = ei;
    const int* col = ei + E;

    int dev = 0, sms = 148, occ = 2;
    cudaGetDevice(&dev);
    cudaDeviceGetAttribute(&sms, cudaDevAttrMultiProcessorCount, dev);
    cudaOccupancyMaxActiveBlocksPerMultiprocessor(&occ, k_mega, 256, 0);
    if (occ < 1) occ = 1;
    int grid = occ * sms;
    if (grid > 1024) grid = 1024;   // plenty of parallelism; keep barrier cheap

    k_mega<<<grid, 256>>>(x, row, col, W1, b1, W2, b2, out, n, E);
}

// round 10
// speedup vs baseline: 1.5350x; 1.5350x over previous
#include <cuda_runtime.h>
#include <cuda_fp16.h>
#include <math.h>

#define NMAX 100000
#define FD   64
#define EMAX 1000000

// ---------------------------------------------------------------------------
// Scratch (__device__ globals; no allocation allowed)
// ---------------------------------------------------------------------------
__device__ __align__(256) __half g_z[NMAX * FD];   // dinv-scaled transformed feats (fp16)
__device__ __align__(256) float  g_h[NMAX * FD];   // layer-1 output (relu'd, fp32)
__device__ float g_dinv[NMAX];
__device__ int   g_cnt[NMAX];
__device__ int   g_start[NMAX];
__device__ int   g_cursor[NMAX];
__device__ int   g_srcs[EMAX];
__device__ int   g_bsum[1024];
__device__ int   g_bar_arrive;
__device__ int   g_bar_gen;

// ---------------------------------------------------------------------------
// Grid-wide barrier (all blocks co-resident by construction)
// ---------------------------------------------------------------------------
__device__ __forceinline__ void gbar(int nblocks) {
    __syncthreads();
    if (threadIdx.x == 0) {
        __threadfence();
        int gen = *(volatile int*)&g_bar_gen;
        if (atomicAdd(&g_bar_arrive, 1) == nblocks - 1) {
            *(volatile int*)&g_bar_arrive = 0;
            __threadfence();
            atomicAdd(&g_bar_gen, 1);
        } else {
            while (*(volatile int*)&g_bar_gen == gen) {}
        }
        __threadfence();
    }
    __syncthreads();
}

__device__ __forceinline__ int block_scan_incl(int v, int* sh) {
    int t = threadIdx.x;
    sh[t] = v; __syncthreads();
    #pragma unroll
    for (int off = 1; off < 256; off <<= 1) {
        int x = (t >= off) ? sh[t - off] : 0;
        __syncthreads();
        sh[t] += x;
        __syncthreads();
    }
    return sh[t];
}

// ---------------------------------------------------------------------------
// Persistent prep kernel: zero -> count -> scan (+dinv) -> fill  (low regs)
// ---------------------------------------------------------------------------
__global__ void __launch_bounds__(256)
k_prep(const int* __restrict__ row, const int* __restrict__ col, int n, int E) {
    __shared__ int sh[256];
    const int t = threadIdx.x;
    const int gtid = blockIdx.x * 256 + t;
    const int gstride = gridDim.x * 256;
    const int NB = gridDim.x;

    for (int i = gtid; i < n; i += gstride) g_cnt[i] = 0;
    gbar(NB);

    for (int e = gtid; e < E; e += gstride) atomicAdd(&g_cnt[col[e]], 1);
    gbar(NB);

    int nchunks = (n + 255) >> 8;
    for (int c = blockIdx.x; c < nchunks; c += gridDim.x) {
        int i = (c << 8) + t;
        int v = (i < n) ? g_cnt[i] : 0;
        if (i < n) g_dinv[i] = rsqrtf((float)(v + 1));
        int incl = block_scan_incl(v, sh);
        if (i < n) g_start[i] = incl - v;
        if (t == 255) g_bsum[c] = incl;
        __syncthreads();
    }
    gbar(NB);

    if (blockIdx.x == 0) {
        int carry = 0;
        for (int base = 0; base < nchunks; base += 256) {
            int idx = base + t;
            int v = (idx < nchunks) ? g_bsum[idx] : 0;
            int incl = block_scan_incl(v, sh);
            if (idx < nchunks) g_bsum[idx] = incl - v + carry;
            __syncthreads();
            carry += sh[255];
            __syncthreads();
        }
    }
    gbar(NB);

    for (int i = gtid; i < n; i += gstride) {
        int s = g_start[i] + g_bsum[i >> 8];
        g_start[i] = s;
        g_cursor[i] = s;
    }
    gbar(NB);

    for (int e = gtid; e < E; e += gstride) {
        int pos = atomicAdd(&g_cursor[col[e]], 1);
        g_srcs[pos] = row[e];
    }
}

// ---------------------------------------------------------------------------
// Tensor-core GEMM: Zh[r,:] = half( (X[r,:] @ W) * dinv[r] )
//   fp16 inputs (converted on load), fp32 accumulate (HMMA m16n8k16).
//   Block = 128 threads (4 warps), 128 rows per block. Warp w: rows w*32..+31.
// ---------------------------------------------------------------------------
#define XPAD 72   // halves per row (64 + 8 pad); 144B row stride

__device__ __forceinline__ void ldsm_x4(unsigned &r0, unsigned &r1,
                                        unsigned &r2, unsigned &r3, unsigned addr) {
    asm volatile("ldmatrix.sync.aligned.m8n8.x4.shared.b16 {%0,%1,%2,%3}, [%4];"
                 : "=r"(r0), "=r"(r1), "=r"(r2), "=r"(r3) : "r"(addr));
}
__device__ __forceinline__ void ldsm_x2t(unsigned &r0, unsigned &r1, unsigned addr) {
    asm volatile("ldmatrix.sync.aligned.m8n8.x2.trans.shared.b16 {%0,%1}, [%2];"
                 : "=r"(r0), "=r"(r1) : "r"(addr));
}
__device__ __forceinline__ void mma16816(float c[4], unsigned a0, unsigned a1,
                                         unsigned a2, unsigned a3,
                                         unsigned b0, unsigned b1) {
    asm volatile("mma.sync.aligned.m16n8k16.row.col.f32.f16.f16.f32 "
                 "{%0,%1,%2,%3},{%4,%5,%6,%7},{%8,%9},{%0,%1,%2,%3};"
                 : "+f"(c[0]), "+f"(c[1]), "+f"(c[2]), "+f"(c[3])
                 : "r"(a0), "r"(a1), "r"(a2), "r"(a3), "r"(b0), "r"(b1));
}

__global__ void __launch_bounds__(128)
k_gemm_tc(const float* __restrict__ X, const float* __restrict__ W,
          const float* __restrict__ dinv, __half* __restrict__ Z, int n) {
    __shared__ __half Xh[128][XPAD];
    __shared__ __half Wh[64][XPAD];
    const int t = threadIdx.x;
    const int warp = t >> 5, lane = t & 31;
    const int r0 = blockIdx.x * 128;

    // load W (64x64 fp32 -> fp16)
    #pragma unroll
    for (int q = t; q < 64 * 16; q += 128) {      // 16 quads per row
        int r = q >> 4, c4 = (q & 15) * 4;
        float4 v = *reinterpret_cast<const float4*>(W + r * 64 + c4);
        __half2 h0 = __floats2half2_rn(v.x, v.y);
        __half2 h1 = __floats2half2_rn(v.z, v.w);
        *reinterpret_cast<__half2*>(&Wh[r][c4])     = h0;
        *reinterpret_cast<__half2*>(&Wh[r][c4 + 2]) = h1;
    }
    // load X tile (128x64 fp32 -> fp16)
    #pragma unroll
    for (int q = t; q < 128 * 16; q += 128) {
        int r = q >> 4, c4 = (q & 15) * 4;
        int gr = r0 + r;
        float4 v = (gr < n) ? *reinterpret_cast<const float4*>(X + (size_t)gr * FD + c4)
                            : make_float4(0.f, 0.f, 0.f, 0.f);
        __half2 h0 = __floats2half2_rn(v.x, v.y);
        __half2 h1 = __floats2half2_rn(v.z, v.w);
        *reinterpret_cast<__half2*>(&Xh[r][c4])     = h0;
        *reinterpret_cast<__half2*>(&Xh[r][c4 + 2]) = h1;
    }
    __syncthreads();

    float acc[2][8][4] = {};   // [rowTile 0/16][n0/8][frag]

    const int wrow = warp * 32;
    #pragma unroll
    for (int ks = 0; ks < 4; ks++) {
        const int k0 = ks * 16;
        // A fragments for this warp's two 16-row tiles
        unsigned a[2][4];
        #pragma unroll
        for (int rt = 0; rt < 2; rt++) {
            int tile = lane >> 3;                 // 0..3
            int row_off = (tile & 1) * 8;
            int k_off   = (tile >> 1) * 8;
            unsigned addr = (unsigned)__cvta_generic_to_shared(
                &Xh[wrow + rt * 16 + row_off + (lane & 7)][k0 + k_off]);
            ldsm_x4(a[rt][0], a[rt][1], a[rt][2], a[rt][3], addr);
        }
        #pragma unroll
        for (int nb = 0; nb < 8; nb++) {
            int krow = k0 + (lane & 7) + ((lane & 8) ? 8 : 0);
            if (krow > k0 + 15) krow = k0 + 15;   // lanes 16-31 unused; keep valid
            unsigned baddr = (unsigned)__cvta_generic_to_shared(&Wh[krow][nb * 8]);
            unsigned b0, b1;
            ldsm_x2t(b0, b1, baddr);
            mma16816(acc[0][nb], a[0][0], a[0][1], a[0][2], a[0][3], b0, b1);
            mma16816(acc[1][nb], a[1][0], a[1][1], a[1][2], a[1][3], b0, b1);
        }
    }

    // epilogue: scale by dinv, convert to fp16, store
    const int gid = lane >> 2, tig = lane & 3;
    #pragma unroll
    for (int rt = 0; rt < 2; rt++) {
        int rA = r0 + wrow + rt * 16 + gid;       // rows gid, gid+8
        int rB = rA + 8;
        float sA = (rA < n) ? dinv[rA] : 0.f;
        float sB = (rB < n) ? dinv[rB] : 0.f;
        #pragma unroll
        for (int nb = 0; nb < 8; nb++) {
            int c = nb * 8 + tig * 2;
            if (rA < n) {
                __half2 h = __floats2half2_rn(acc[rt][nb][0] * sA, acc[rt][nb][1] * sA);
                *reinterpret_cast<__half2*>(Z + (size_t)rA * FD + c) = h;
            }
            if (rB < n) {
                __half2 h = __floats2half2_rn(acc[rt][nb][2] * sB, acc[rt][nb][3] * sB);
                *reinterpret_cast<__half2*>(Z + (size_t)rB * FD + c) = h;
            }
        }
    }
}

// ---------------------------------------------------------------------------
// Pull aggregation (fp16 gathers, fp32 accum) — unchanged from R8
// ---------------------------------------------------------------------------
__device__ __forceinline__ void acc_add8(float a[8], uint4 v) {
    __half2* p = reinterpret_cast<__half2*>(&v);
    #pragma unroll
    for (int q = 0; q < 4; q++) {
        float2 f = __half22float2(p[q]);
        a[q * 2 + 0] += f.x;
        a[q * 2 + 1] += f.y;
    }
}

__global__ void k_agg(const __half* __restrict__ zs,
                      const int* __restrict__ srcs,
                      const int* __restrict__ startv,
                      const int* __restrict__ cnt,
                      const float* __restrict__ dinv,
                      const float* __restrict__ bias,
                      float* __restrict__ outp, int n) {
    int tid  = blockIdx.x * blockDim.x + threadIdx.x;
    int node = tid >> 3;
    if (node >= n) return;
    int lane = tid & 7;

    const uint4* zq = reinterpret_cast<const uint4*>(zs);
    int s = startv[node];
    int m = cnt[node];
    float d = dinv[node];

    float a[8] = {};
    acc_add8(a, zq[(size_t)node * 8 + lane]);   // self loop

    int i = 0;
    for (; i + 4 <= m; i += 4) {
        int r0 = srcs[s + i + 0];
        int r1 = srcs[s + i + 1];
        int r2 = srcs[s + i + 2];
        int r3 = srcs[s + i + 3];
        uint4 v0 = zq[(size_t)r0 * 8 + lane];
        uint4 v1 = zq[(size_t)r1 * 8 + lane];
        uint4 v2 = zq[(size_t)r2 * 8 + lane];
        uint4 v3 = zq[(size_t)r3 * 8 + lane];
        acc_add8(a, v0); acc_add8(a, v1);
        acc_add8(a, v2); acc_add8(a, v3);
    }
    for (; i < m; i++) {
        int r = srcs[s + i];
        acc_add8(a, zq[(size_t)r * 8 + lane]);
    }

    float4 b0 = reinterpret_cast<const float4*>(bias)[lane * 2 + 0];
    float4 b1 = reinterpret_cast<const float4*>(bias)[lane * 2 + 1];
    float4 o0 = make_float4(fmaxf(fmaf(a[0], d, b0.x), 0.f),
                            fmaxf(fmaf(a[1], d, b0.y), 0.f),
                            fmaxf(fmaf(a[2], d, b0.z), 0.f),
                            fmaxf(fmaf(a[3], d, b0.w), 0.f));
    float4 o1 = make_float4(fmaxf(fmaf(a[4], d, b1.x), 0.f),
                            fmaxf(fmaf(a[5], d, b1.y), 0.f),
                            fmaxf(fmaf(a[6], d, b1.z), 0.f),
                            fmaxf(fmaf(a[7], d, b1.w), 0.f));
    float4* po = reinterpret_cast<float4*>(outp + (size_t)node * FD + lane * 8);
    po[0] = o0;
    po[1] = o1;
}

// ---------------------------------------------------------------------------
// Launch: 5 kernels
// ---------------------------------------------------------------------------
extern "C" void kernel_launch(void* const* d_in, const int* in_sizes, int n_in,
                              void* d_out, int out_size) {
    const float* x  = (const float*)d_in[0];
    const int*   ei = (const int*)d_in[1];
    const float* W1 = (const float*)d_in[2];
    const float* b1 = (const float*)d_in[3];
    const float* W2 = (const float*)d_in[4];
    const float* b2 = (const float*)d_in[5];
    float*       out = (float*)d_out;

    const int n = in_sizes[0] / FD;     // 100000
    const int E = in_sizes[1] / 2;      // 1000000
    const int* row = ei;
    const int* col = ei + E;

    __half* z; float *h, *dinv;
    int *cnt, *startv, *srcs;
    cudaGetSymbolAddress((void**)&z,      g_z);
    cudaGetSymbolAddress((void**)&h,      g_h);
    cudaGetSymbolAddress((void**)&dinv,   g_dinv);
    cudaGetSymbolAddress((void**)&cnt,    g_cnt);
    cudaGetSymbolAddress((void**)&startv, g_start);
    cudaGetSymbolAddress((void**)&srcs,   g_srcs);

    int dev = 0, sms = 148, occP = 4;
    cudaGetDevice(&dev);
    cudaDeviceGetAttribute(&sms, cudaDevAttrMultiProcessorCount, dev);
    cudaOccupancyMaxActiveBlocksPerMultiprocessor(&occP, k_prep, 256, 0);
    if (occP < 1) occP = 1;
    int gridP = occP * sms;
    if (gridP > 1024) gridP = 1024;

    const int gGemm = (n + 127) / 128;
    const int gAgg  = (int)(((long long)n * 8 + 255) / 256);

    k_prep   <<<gridP, 256>>>(row, col, n, E);

    k_gemm_tc<<<gGemm, 128>>>(x, W1, dinv, z, n);
    k_agg    <<<gAgg, 256>>>(z, srcs, startv, cnt, dinv, b1, h, n);

    k_gemm_tc<<<gGemm, 128>>>(h, W2, dinv, z, n);
    k_agg    <<<gAgg, 256>>>(z, srcs, startv, cnt, dinv, b2, out, n);
}

// round 11
// speedup vs baseline: 1.7236x; 1.1229x over previous
#include <cuda_runtime.h>
#include <cuda_fp16.h>
#include <math.h>

#define NMAX 100000
#define FD   64
#define EMAX 1000000

// ---------------------------------------------------------------------------
// Scratch
// ---------------------------------------------------------------------------
__device__ __align__(256) __half g_z[NMAX * FD];   // unscaled transformed feats (fp16)
__device__ __align__(256) __half g_h[NMAX * FD];   // layer-1 output (relu'd, fp16)
__device__ float g_dinv[NMAX];
__device__ int   g_cnt[NMAX];
__device__ int   g_start[NMAX];
__device__ int   g_cursor[NMAX];
__device__ int   g_srcs[EMAX];
__device__ int   g_bsum[1024];
__device__ int   g_bar_arrive;
__device__ int   g_bar_gen;

// ---------------------------------------------------------------------------
// Barrier over the first P blocks (all co-resident by construction)
// ---------------------------------------------------------------------------
__device__ __forceinline__ void gbar(int nblocks) {
    __syncthreads();
    if (threadIdx.x == 0) {
        __threadfence();
        int gen = *(volatile int*)&g_bar_gen;
        if (atomicAdd(&g_bar_arrive, 1) == nblocks - 1) {
            *(volatile int*)&g_bar_arrive = 0;
            __threadfence();
            atomicAdd(&g_bar_gen, 1);
        } else {
            while (*(volatile int*)&g_bar_gen == gen) {}
        }
        __threadfence();
    }
    __syncthreads();
}

__device__ __forceinline__ int block_scan_incl128(int v, int* sh) {
    int t = threadIdx.x;
    sh[t] = v; __syncthreads();
    #pragma unroll
    for (int off = 1; off < 128; off <<= 1) {
        int x = (t >= off) ? sh[t - off] : 0;
        __syncthreads();
        sh[t] += x;
        __syncthreads();
    }
    return sh[t];
}

// ---------------------------------------------------------------------------
// HMMA helpers
// ---------------------------------------------------------------------------
#define XPAD 72   // halves per row (64 + 8 pad)

__device__ __forceinline__ void ldsm_x4(unsigned &r0, unsigned &r1,
                                        unsigned &r2, unsigned &r3, unsigned addr) {
    asm volatile("ldmatrix.sync.aligned.m8n8.x4.shared.b16 {%0,%1,%2,%3}, [%4];"
                 : "=r"(r0), "=r"(r1), "=r"(r2), "=r"(r3) : "r"(addr));
}
__device__ __forceinline__ void ldsm_x2t(unsigned &r0, unsigned &r1, unsigned addr) {
    asm volatile("ldmatrix.sync.aligned.m8n8.x2.trans.shared.b16 {%0,%1}, [%2];"
                 : "=r"(r0), "=r"(r1) : "r"(addr));
}
__device__ __forceinline__ void mma16816(float c[4], unsigned a0, unsigned a1,
                                         unsigned a2, unsigned a3,
                                         unsigned b0, unsigned b1) {
    asm volatile("mma.sync.aligned.m16n8k16.row.col.f32.f16.f16.f32 "
                 "{%0,%1,%2,%3},{%4,%5,%6,%7},{%8,%9},{%0,%1,%2,%3};"
                 : "+f"(c[0]), "+f"(c[1]), "+f"(c[2]), "+f"(c[3])
                 : "r"(a0), "r"(a1), "r"(a2), "r"(a3), "r"(b0), "r"(b1));
}

// Load W (fp32 64x64) into Wh
__device__ __forceinline__ void load_W(const float* __restrict__ W,
                                       __half (*Wh)[XPAD], int t) {
    #pragma unroll
    for (int q = t; q < 64 * 16; q += 128) {
        int r = q >> 4, c4 = (q & 15) * 4;
        float4 v = *reinterpret_cast<const float4*>(W + r * 64 + c4);
        *reinterpret_cast<__half2*>(&Wh[r][c4])     = __floats2half2_rn(v.x, v.y);
        *reinterpret_cast<__half2*>(&Wh[r][c4 + 2]) = __floats2half2_rn(v.z, v.w);
    }
}

// One 128-row MMA tile: Xh (loaded) @ Wh -> Z[r0..r0+127]
__device__ void gemm_tile(__half (*Xh)[XPAD], __half (*Wh)[XPAD],
                          __half* __restrict__ Z, int r0, int n,
                          int warp, int lane) {
    float acc[2][8][4] = {};
    const int wrow = warp * 32;
    #pragma unroll
    for (int ks = 0; ks < 4; ks++) {
        const int k0 = ks * 16;
        unsigned a[2][4];
        #pragma unroll
        for (int rt = 0; rt < 2; rt++) {
            int tile = lane >> 3;
            int row_off = (tile & 1) * 8;
            int k_off   = (tile >> 1) * 8;
            unsigned addr = (unsigned)__cvta_generic_to_shared(
                &Xh[wrow + rt * 16 + row_off + (lane & 7)][k0 + k_off]);
            ldsm_x4(a[rt][0], a[rt][1], a[rt][2], a[rt][3], addr);
        }
        #pragma unroll
        for (int nb = 0; nb < 8; nb++) {
            int krow = k0 + (lane & 7) + ((lane & 8) ? 8 : 0);
            if (krow > k0 + 15) krow = k0 + 15;
            unsigned baddr = (unsigned)__cvta_generic_to_shared(&Wh[krow][nb * 8]);
            unsigned b0, b1;
            ldsm_x2t(b0, b1, baddr);
            mma16816(acc[0][nb], a[0][0], a[0][1], a[0][2], a[0][3], b0, b1);
            mma16816(acc[1][nb], a[1][0], a[1][1], a[1][2], a[1][3], b0, b1);
        }
    }
    const int gid = lane >> 2, tig = lane & 3;
    #pragma unroll
    for (int rt = 0; rt < 2; rt++) {
        int rA = r0 + wrow + rt * 16 + gid;
        int rB = rA + 8;
        #pragma unroll
        for (int nb = 0; nb < 8; nb++) {
            int c = nb * 8 + tig * 2;
            if (rA < n)
                *reinterpret_cast<__half2*>(Z + (size_t)rA * FD + c) =
                    __floats2half2_rn(acc[rt][nb][0], acc[rt][nb][1]);
            if (rB < n)
                *reinterpret_cast<__half2*>(Z + (size_t)rB * FD + c) =
                    __floats2half2_rn(acc[rt][nb][2], acc[rt][nb][3]);
        }
    }
}

// ---------------------------------------------------------------------------
// Fused kernel: blocks [0,P) run prep (CSR + dinv); blocks [P,NB) run gemm1.
// ---------------------------------------------------------------------------
__global__ void __launch_bounds__(128)
k_prep_gemm1(const float* __restrict__ x, const float* __restrict__ W1,
             const int* __restrict__ row, const int* __restrict__ col,
             int n, int E, int P) {
    __shared__ __half Xh[128][XPAD];
    __shared__ __half Wh[64][XPAD];
    __shared__ int sh[128];
    const int t = threadIdx.x;

    if (blockIdx.x >= P) {
        // ---- gemm1 role ----
        const int warp = t >> 5, lane = t & 31;
        load_W(W1, Wh, t);
        int ntiles = (n + 127) >> 7;
        int nbg = gridDim.x - P;
        for (int tile = blockIdx.x - P; tile < ntiles; tile += nbg) {
            int r0 = tile << 7;
            __syncthreads();
            #pragma unroll
            for (int q = t; q < 128 * 16; q += 128) {
                int r = q >> 4, c4 = (q & 15) * 4;
                int gr = r0 + r;
                float4 v = (gr < n) ? *reinterpret_cast<const float4*>(x + (size_t)gr * FD + c4)
                                    : make_float4(0.f, 0.f, 0.f, 0.f);
                *reinterpret_cast<__half2*>(&Xh[r][c4])     = __floats2half2_rn(v.x, v.y);
                *reinterpret_cast<__half2*>(&Xh[r][c4 + 2]) = __floats2half2_rn(v.z, v.w);
            }
            __syncthreads();
            gemm_tile(Xh, Wh, g_z, r0, n, warp, lane);
        }
        return;
    }

    // ---- prep role (P blocks, barrier over P) ----
    const int gtid = blockIdx.x * 128 + t;
    const int gstride = P * 128;

    for (int i = gtid; i < n; i += gstride) g_cnt[i] = 0;
    gbar(P);

    for (int e = gtid; e < E; e += gstride) atomicAdd(&g_cnt[col[e]], 1);
    gbar(P);

    int nchunks = (n + 127) >> 7;
    for (int c = blockIdx.x; c < nchunks; c += P) {
        int i = (c << 7) + t;
        int v = (i < n) ? g_cnt[i] : 0;
        if (i < n) g_dinv[i] = rsqrtf((float)(v + 1));
        int incl = block_scan_incl128(v, sh);
        if (i < n) g_start[i] = incl - v;
        if (t == 127) g_bsum[c] = incl;
        __syncthreads();
    }
    gbar(P);

    if (blockIdx.x == 0) {
        int carry = 0;
        for (int base = 0; base < nchunks; base += 128) {
            int idx = base + t;
            int v = (idx < nchunks) ? g_bsum[idx] : 0;
            int incl = block_scan_incl128(v, sh);
            if (idx < nchunks) g_bsum[idx] = incl - v + carry;
            __syncthreads();
            carry += sh[127];
            __syncthreads();
        }
    }
    gbar(P);

    for (int i = gtid; i < n; i += gstride) {
        int s = g_start[i] + g_bsum[i >> 7];
        g_start[i] = s;
        g_cursor[i] = s;
    }
    gbar(P);

    for (int e = gtid; e < E; e += gstride) {
        int pos = atomicAdd(&g_cursor[col[e]], 1);
        g_srcs[pos] = row[e];
    }
}

// ---------------------------------------------------------------------------
// gemm2: fp16 input (h), fp16 output (z). One 128-row tile per block.
// ---------------------------------------------------------------------------
__global__ void __launch_bounds__(128)
k_gemm2(const __half* __restrict__ H, const float* __restrict__ W,
        __half* __restrict__ Z, int n) {
    __shared__ __half Xh[128][XPAD];
    __shared__ __half Wh[64][XPAD];
    const int t = threadIdx.x;
    const int warp = t >> 5, lane = t & 31;
    const int r0 = blockIdx.x << 7;

    load_W(W, Wh, t);
    #pragma unroll
    for (int q = t; q < 128 * 8; q += 128) {        // 8 uint4 per row
        int r = q >> 3, c8 = (q & 7) * 8;
        int gr = r0 + r;
        uint4 v = (gr < n) ? *reinterpret_cast<const uint4*>(H + (size_t)gr * FD + c8)
                           : make_uint4(0, 0, 0, 0);
        *reinterpret_cast<uint4*>(&Xh[r][c8]) = v;
    }
    __syncthreads();
    gemm_tile(Xh, Wh, Z, r0, n, warp, lane);
}

// ---------------------------------------------------------------------------
// Pull aggregation (fp16 gathers scaled by dinv[src], fp32 accum)
//   out[c,:] = relu( (sum_{r in {c} u in(c)} z[r,:]*dinv[r]) * dinv[c] + b )
// ---------------------------------------------------------------------------
__device__ __forceinline__ void acc_fma8(float a[8], uint4 v, float s) {
    __half2* p = reinterpret_cast<__half2*>(&v);
    #pragma unroll
    for (int q = 0; q < 4; q++) {
        float2 f = __half22float2(p[q]);
        a[q * 2 + 0] = fmaf(f.x, s, a[q * 2 + 0]);
        a[q * 2 + 1] = fmaf(f.y, s, a[q * 2 + 1]);
    }
}

template <bool HALF_OUT>
__global__ void k_agg(const __half* __restrict__ zs,
                      const int* __restrict__ srcs,
                      const int* __restrict__ startv,
                      const int* __restrict__ cnt,
                      const float* __restrict__ dinv,
                      const float* __restrict__ bias,
                      void* __restrict__ outp, int n) {
    int tid  = blockIdx.x * blockDim.x + threadIdx.x;
    int node = tid >> 3;
    if (node >= n) return;
    int lane = tid & 7;

    const uint4* zq = reinterpret_cast<const uint4*>(zs);
    int s = startv[node];
    int m = cnt[node];
    float d = dinv[node];

    float a[8] = {};
    acc_fma8(a, zq[(size_t)node * 8 + lane], d);   // self loop

    int i = 0;
    for (; i + 4 <= m; i += 4) {
        int r0 = srcs[s + i + 0];
        int r1 = srcs[s + i + 1];
        int r2 = srcs[s + i + 2];
        int r3 = srcs[s + i + 3];
        float s0 = dinv[r0], s1 = dinv[r1], s2 = dinv[r2], s3 = dinv[r3];
        uint4 v0 = zq[(size_t)r0 * 8 + lane];
        uint4 v1 = zq[(size_t)r1 * 8 + lane];
        uint4 v2 = zq[(size_t)r2 * 8 + lane];
        uint4 v3 = zq[(size_t)r3 * 8 + lane];
        acc_fma8(a, v0, s0); acc_fma8(a, v1, s1);
        acc_fma8(a, v2, s2); acc_fma8(a, v3, s3);
    }
    for (; i < m; i++) {
        int r = srcs[s + i];
        acc_fma8(a, zq[(size_t)r * 8 + lane], dinv[r]);
    }

    float4 b0 = reinterpret_cast<const float4*>(bias)[lane * 2 + 0];
    float4 b1 = reinterpret_cast<const float4*>(bias)[lane * 2 + 1];
    float o[8];
    o[0] = fmaxf(fmaf(a[0], d, b0.x), 0.f); o[1] = fmaxf(fmaf(a[1], d, b0.y), 0.f);
    o[2] = fmaxf(fmaf(a[2], d, b0.z), 0.f); o[3] = fmaxf(fmaf(a[3], d, b0.w), 0.f);
    o[4] = fmaxf(fmaf(a[4], d, b1.x), 0.f); o[5] = fmaxf(fmaf(a[5], d, b1.y), 0.f);
    o[6] = fmaxf(fmaf(a[6], d, b1.z), 0.f); o[7] = fmaxf(fmaf(a[7], d, b1.w), 0.f);

    if (HALF_OUT) {
        __half2 hs[4];
        #pragma unroll
        for (int q = 0; q < 4; q++) hs[q] = __floats2half2_rn(o[q * 2], o[q * 2 + 1]);
        reinterpret_cast<uint4*>((__half*)outp + (size_t)node * FD + lane * 8)[0] =
            *reinterpret_cast<uint4*>(hs);
    } else {
        float4* po = reinterpret_cast<float4*>((float*)outp + (size_t)node * FD + lane * 8);
        po[0] = make_float4(o[0], o[1], o[2], o[3]);
        po[1] = make_float4(o[4], o[5], o[6], o[7]);
    }
}

// ---------------------------------------------------------------------------
// Launch: 4 kernels
// ---------------------------------------------------------------------------
extern "C" void kernel_launch(void* const* d_in, const int* in_sizes, int n_in,
                              void* d_out, int out_size) {
    const float* x  = (const float*)d_in[0];
    const int*   ei = (const int*)d_in[1];
    const float* W1 = (const float*)d_in[2];
    const float* b1 = (const float*)d_in[3];
    const float* W2 = (const float*)d_in[4];
    const float* b2 = (const float*)d_in[5];
    float*       out = (float*)d_out;

    const int n = in_sizes[0] / FD;     // 100000
    const int E = in_sizes[1] / 2;      // 1000000
    const int* row = ei;
    const int* col = ei + E;

    __half *z, *h; float* dinv;
    int *cnt, *startv, *srcs;
    cudaGetSymbolAddress((void**)&z,      g_z);
    cudaGetSymbolAddress((void**)&h,      g_h);
    cudaGetSymbolAddress((void**)&dinv,   g_dinv);
    cudaGetSymbolAddress((void**)&cnt,    g_cnt);
    cudaGetSymbolAddress((void**)&startv, g_start);
    cudaGetSymbolAddress((void**)&srcs,   g_srcs);

    int dev = 0, sms = 148, occ = 5;
    cudaGetDevice(&dev);
    cudaDeviceGetAttribute(&sms, cudaDevAttrMultiProcessorCount, dev);
    cudaOccupancyMaxActiveBlocksPerMultiprocessor(&occ, k_prep_gemm1, 128, 0);
    if (occ < 2) occ = 2;
    int NB = occ * sms;
    int P  = (NB * 3) / 5;              // ~60% of blocks to prep
    if (P < 1) P = 1;
    if (NB - P < 1) P = NB - 1;

    const int gGemm = (n + 127) / 128;  // 782
    const int gAgg  = (int)(((long long)n * 8 + 255) / 256);

    k_prep_gemm1<<<NB, 128>>>(x, W1, row, col, n, E, P);
    k_agg<true> <<<gAgg, 256>>>(z, srcs, startv, cnt, dinv, b1, h, n);
    k_gemm2     <<<gGemm, 128>>>(h, W2, z, n);
    k_agg<false><<<gAgg, 256>>>(z, srcs, startv, cnt, dinv, b2, out, n);
}